// round 10
// baseline (speedup 1.0000x reference)
#include <cuda_runtime.h>
#include <cstdint>

// out[c, i, j] = one_hot[i, c]      for c in [0,4)
// out[c, i, j] = one_hot[j, c-4]    for c in [4,8)
// one_hot: [L, 4] float32, L = 4096; out: [8, L, L] float32 (536.9 MB stores)
//
// R9 neutral -> STG-path micro-variants exhausted (DRAM pinned ~82%).
// R10: bottom planes emit via TMA bulk stores: stage 4KB channel segment in
// smem once, thread0 issues 4x cp.async.bulk (4KB linear bursts) to the 4
// rows of the strip. Store-side L1 wavefronts vanish; DRAM sees long
// contiguous bursts. Top planes keep the proven direct-STG full-row path.

#define BLOCK 256
#define ROWS  4
#define SEGS  4          // L4 / BLOCK for L=4096

__global__ __launch_bounds__(BLOCK, 8)
void seq_embed_kernel(const float* __restrict__ oh, float4* __restrict__ out, int L)
{
    const int c  = blockIdx.z;                              // 0..7 plane (uniform per block)
    const int L4 = L >> 2;

    if (c < 4) {
        // One block = one full row (16KB contiguous). Thread stores SEGS
        // consecutive 4KB segments of that row; value loaded once.
        const int row = blockIdx.y * SEGS + blockIdx.x;     // 0..L-1
        const float val = __ldg(&oh[row * 4 + c]);
        const float4 v = make_float4(val, val, val, val);

        float4* p = out + ((size_t)c * L + (size_t)row) * (size_t)L4 + threadIdx.x;
#pragma unroll
        for (int s = 0; s < SEGS; s++) {
            __stcs(p, v);
            p += BLOCK;
        }
    } else {
        // Column one-hot via TMA bulk store.
        // Block (c, strip i0, segment x) stages channel cc of one_hot rows
        // [4*jbase, 4*jbase + 1024) = 4KB in smem (coalesced LDG.128 ->
        // extract -> stride-1 STS), then thread 0 fans it out to the 4 rows
        // with cp.async.bulk 4KB linear bursts.
        __shared__ __align__(16) float sch[4 * BLOCK];      // 4 KB
        const int i0    = blockIdx.y * ROWS;                // row-strip base
        const int jbase = blockIdx.x * BLOCK;               // float4-column base of segment
        const int cc    = c - 4;
        const float4* ohf4 = reinterpret_cast<const float4*>(oh);

#pragma unroll
        for (int q = 0; q < 4; q++) {
            const float4 rv = __ldg(&ohf4[4 * jbase + q * BLOCK + threadIdx.x]);
            sch[q * BLOCK + threadIdx.x] =
                (cc & 1) ? ((cc & 2) ? rv.w : rv.y)
                         : ((cc & 2) ? rv.z : rv.x);
        }
        // Order generic-proxy smem writes before async-proxy reads.
        asm volatile("fence.proxy.async.shared::cta;" ::: "memory");
        __syncthreads();

        if (threadIdx.x == 0) {
            uint32_t saddr;
            asm("{ .reg .u64 t; cvta.to.shared.u64 t, %1; cvt.u32.u64 %0, t; }"
                : "=r"(saddr) : "l"(sch));
            float4* p = out + ((size_t)c * L + (size_t)i0) * (size_t)L4 + (size_t)jbase;
#pragma unroll
            for (int r = 0; r < ROWS; r++) {
                asm volatile(
                    "cp.async.bulk.global.shared::cta.bulk_group [%0], [%1], %2;"
                    :: "l"(p), "r"(saddr), "n"(4 * BLOCK * 4) : "memory");
                p += L4;
            }
            asm volatile("cp.async.bulk.commit_group;" ::: "memory");
            asm volatile("cp.async.bulk.wait_group 0;" ::: "memory");
        }
    }
}

extern "C" void kernel_launch(void* const* d_in, const int* in_sizes, int n_in,
                              void* d_out, int out_size)
{
    const float* oh = (const float*)d_in[0];
    const int L  = in_sizes[0] / 4;   // one_hot is [L, 4]
    const int L4 = L >> 2;

    dim3 block(BLOCK);
    dim3 grid(L4 / BLOCK, L / ROWS, 8);   // (4, 1024, 8) = 32768 blocks for L=4096
    seq_embed_kernel<<<grid, block>>>(oh, (float4*)d_out, L);
}